// round 10
// baseline (speedup 1.0000x reference)
#include <cuda_runtime.h>
#include <cuda_fp16.h>
#include <cuda_bf16.h>
#include <stdint.h>

#define N_RAYS   4096
#define N_INTERS 1536
#define NSAMP    1535          // N_INTERS - 1
#define RESV     128
#define CHAN     28
#define NVOX     (128*128*128)
#define CHSTRIDE NVOX
#define TR_BLOCKS (NVOX / 256)   // 8192 transpose blocks

__device__ int    g_ray_count[N_RAYS];
__device__ int    g_ray_base[N_RAYS];
__device__ int    g_map[(size_t)N_RAYS * NSAMP];   // oidx -> (ray<<11)|j
struct RayPack { float4 o_start; float4 d; };
__device__ RayPack g_raypack[N_RAYS];

// channel-last fp16 grid: voxel record = 28 halves + 4 pad = 64B = 4x uint4
__device__ uint4 g_data64[(size_t)NVOX * 4];

// --- mask-critical math: must be bit-stable under --use_fast_math ---
__device__ __forceinline__ float voxel_len() {
    return __fdiv_rn(__fsqrt_rn(27.0f), 1536.0f);
}

__device__ __forceinline__ float compute_start(float ox, float oy, float oz,
                                               float dx, float dy, float dz) {
    float px = __fdiv_rn(1.5f - ox, dx);
    float py = __fdiv_rn(1.5f - oy, dy);
    float pz = __fdiv_rn(1.5f - oz, dz);
    float nx = __fdiv_rn(-1.5f - ox, dx);
    float ny = __fdiv_rn(-1.5f - oy, dy);
    float nz = __fdiv_rn(-1.5f - oz, dz);
    float ix = fminf(px, nx);
    float iy = fminf(py, ny);
    float iz = fminf(pz, nz);
    float s  = fmaxf(fmaxf(ix, iy), iz);
    return fminf(fmaxf(s, 0.2f), 6.0f);
}

__device__ __forceinline__ float sample_t(float start, int j) {
    return __fadd_rn(start, __fmul_rn((float)j, voxel_len()));
}

__device__ __forceinline__ void point_at(float start, int j,
                                         float ox, float oy, float oz,
                                         float dx, float dy, float dz,
                                         float& px, float& py, float& pz) {
    float t = sample_t(start, j);
    px = __fadd_rn(ox, __fmul_rn(t, dx));
    py = __fadd_rn(oy, __fmul_rn(t, dy));
    pz = __fadd_rn(oz, __fmul_rn(t, dz));
}

__device__ __forceinline__ bool in_box(float px, float py, float pz) {
    return (-1.5f < px) & (px < 1.5f) &
           (-1.5f < py) & (py < 1.5f) &
           (-1.5f < pz) & (pz < 1.5f);
}

// unpack 8 halves (uint4) into 8 floats
__device__ __forceinline__ void unpack8(uint4 u, float* f) {
    float2 t;
    t = __half22float2(*reinterpret_cast<__half2*>(&u.x)); f[0]=t.x; f[1]=t.y;
    t = __half22float2(*reinterpret_cast<__half2*>(&u.y)); f[2]=t.x; f[3]=t.y;
    t = __half22float2(*reinterpret_cast<__half2*>(&u.z)); f[4]=t.x; f[5]=t.y;
    t = __half22float2(*reinterpret_cast<__half2*>(&u.w)); f[6]=t.x; f[7]=t.y;
}

// ============ Kernel 0 (fused): transpose->fp16  +  mask/count/intersections ========
__global__ void __launch_bounds__(256)
k_pre(const float* __restrict__ data,
      const float* __restrict__ rays_o, const float* __restrict__ rays_d,
      float* __restrict__ mask_out, float* __restrict__ intr_out) {
    __shared__ float tile[28][257];
    int tid = threadIdx.x;

    if (blockIdx.x < TR_BLOCKS) {
        // -------- transpose path: 256 voxels per block --------
        int v0 = blockIdx.x * 256;
        #pragma unroll
        for (int c = 0; c < 28; c++)
            tile[c][tid] = __ldg(data + (size_t)c * CHSTRIDE + v0 + tid);
        __syncthreads();
        uint2* out = (uint2*)g_data64;   // voxel record = 8 uint2, write all 8 (full 64B lines)
        #pragma unroll
        for (int k = 0; k < 8; k++) {
            int l  = k * 256 + tid;      // [0, 2048)
            int v  = l >> 3;
            int c4 = l & 7;              // uint2 index 0..7 (7 = zero pad)
            uint2 u;
            if (c4 < 7) {
                __half2 h0 = __floats2half2_rn(tile[4*c4+0][v], tile[4*c4+1][v]);
                __half2 h1 = __floats2half2_rn(tile[4*c4+2][v], tile[4*c4+3][v]);
                u.x = *reinterpret_cast<unsigned*>(&h0);
                u.y = *reinterpret_cast<unsigned*>(&h1);
            } else {
                u.x = 0u; u.y = 0u;
            }
            out[(size_t)(v0 + v) * 8 + c4] = u;
        }
        return;
    }

    // -------- mask path --------
    int ray = blockIdx.x - TR_BLOCKS;
    float ox = rays_o[ray*3+0], oy = rays_o[ray*3+1], oz = rays_o[ray*3+2];
    float dx = rays_d[ray*3+0], dy = rays_d[ray*3+1], dz = rays_d[ray*3+2];
    float start = compute_start(ox, oy, oz, dx, dy, dz);

    if (tid == 0) {
        RayPack rp;
        rp.o_start = make_float4(ox, oy, oz, start);
        rp.d       = make_float4(dx, dy, dz, 0.0f);
        g_raypack[ray] = rp;
    }

    for (int j = tid; j < N_INTERS; j += 256)
        __stcs(intr_out + (size_t)ray * N_INTERS + j, sample_t(start, j));

    int cnt = 0;
    for (int j = tid; j < NSAMP; j += 256) {
        float px, py, pz;
        point_at(start, j, ox, oy, oz, dx, dy, dz, px, py, pz);
        bool m = in_box(px, py, pz);
        __stcs(mask_out + (size_t)ray * NSAMP + j, m ? 1.0f : 0.0f);
        cnt += m;
    }
    int* sh = (int*)tile;  // reuse smem
    for (int o = 16; o > 0; o >>= 1) cnt += __shfl_down_sync(0xffffffffu, cnt, o);
    if ((tid & 31) == 0) sh[tid >> 5] = cnt;
    __syncthreads();
    if (tid == 0) {
        int s = 0;
        #pragma unroll
        for (int w = 0; w < 8; w++) s += sh[w];
        g_ray_count[ray] = s;
    }
}

// =====================  Kernel 2: exclusive scan over 4096 ray counts ================
__global__ void __launch_bounds__(1024)
k_scan() {
    __shared__ int sh[1024];
    int tid = threadIdx.x;
    int c0 = g_ray_count[tid*4+0];
    int c1 = g_ray_count[tid*4+1];
    int c2 = g_ray_count[tid*4+2];
    int c3 = g_ray_count[tid*4+3];
    int tot = c0 + c1 + c2 + c3;
    sh[tid] = tot;
    __syncthreads();
    for (int off = 1; off < 1024; off <<= 1) {
        int v = (tid >= off) ? sh[tid - off] : 0;
        __syncthreads();
        sh[tid] += v;
        __syncthreads();
    }
    int excl = sh[tid] - tot;
    g_ray_base[tid*4+0] = excl;
    g_ray_base[tid*4+1] = excl + c0;
    g_ray_base[tid*4+2] = excl + c0 + c1;
    g_ray_base[tid*4+3] = excl + c0 + c1 + c2;
}

// =====================  Kernel 2b: build oidx -> (ray, j) map  =======================
__global__ void __launch_bounds__(256)
k_build_map() {
    int ray  = blockIdx.x;
    int cnt  = g_ray_count[ray];
    int base = g_ray_base[ray];
    int tag  = ray << 11;
    for (int j = threadIdx.x; j < cnt; j += 256)
        g_map[base + j] = tag | j;
}

// =====================  Kernel 3: flat gather, 2 lanes per sample, fp16 grid =========
// lane sub in {0,1} handles uint4 groups {2sub, 2sub+1} (adjacent 32B of the record)
__global__ void __launch_bounds__(256)
k_gather(float* __restrict__ data_out, float* __restrict__ sub_out, int nm) {
    int gt = blockIdx.x * 256 + threadIdx.x;
    int s   = gt >> 1;
    int sub = gt & 1;
    if (s >= nm) return;

    int info = __ldg(&g_map[s]);
    int ray = info >> 11;
    int j   = info & 2047;

    float4 osr = __ldg(&g_raypack[ray].o_start);
    float4 dd  = __ldg(&g_raypack[ray].d);

    float px, py, pz;
    point_at(osr.w, j, osr.x, osr.y, osr.z, dd.x, dd.y, dd.z, px, py, pz);

    const float INV = 0.66666668653f;  // float(2/3)
    float nx = (px + 1.5f) * INV - 1.0f;
    float ny = (py + 1.5f) * INV - 1.0f;
    float nz = (pz + 1.5f) * INV - 1.0f;

    // trilinear coords
    float x = (nx + 1.0f) * 63.5f;
    float y = (ny + 1.0f) * 63.5f;
    float z = (nz + 1.0f) * 63.5f;
    float x0f = floorf(x), y0f = floorf(y), z0f = floorf(z);
    float fx = x - x0f, fy = y - y0f, fz = z - z0f;
    int ix0 = min(max((int)x0f, 0), 127);
    int iy0 = min(max((int)y0f, 0), 127);
    int iz0 = min(max((int)z0f, 0), 127);
    int ix1 = min(ix0 + 1, 127);
    int iy1 = min(iy0 + 1, 127);
    int iz1 = min(iz0 + 1, 127);

    float gxc = 1.0f - fx, gyc = 1.0f - fy, gzc = 1.0f - fz;
    float w000 = gzc * gyc * gxc;
    float w001 = gzc * gyc * fx;
    float w010 = gzc * fy  * gxc;
    float w011 = gzc * fy  * fx;
    float w100 = fz  * gyc * gxc;
    float w101 = fz  * gyc * fx;
    float w110 = fz  * fy  * gxc;
    float w111 = fz  * fy  * fx;

    int b00 = (iz0 * RESV + iy0) * RESV;
    int b01 = (iz0 * RESV + iy1) * RESV;
    int b10 = (iz1 * RESV + iy0) * RESV;
    int b11 = (iz1 * RESV + iy1) * RESV;

    const uint4* G = g_data64 + 2*sub;
    size_t o000 = ((size_t)(b00 + ix0)) << 2;
    size_t o001 = ((size_t)(b00 + ix1)) << 2;
    size_t o010 = ((size_t)(b01 + ix0)) << 2;
    size_t o011 = ((size_t)(b01 + ix1)) << 2;
    size_t o100 = ((size_t)(b10 + ix0)) << 2;
    size_t o101 = ((size_t)(b10 + ix1)) << 2;
    size_t o110 = ((size_t)(b11 + ix0)) << 2;
    size_t o111 = ((size_t)(b11 + ix1)) << 2;

    // 16 loads: 8 corners x 2 adjacent uint4
    uint4 a0 = __ldg(G + o000),     a1 = __ldg(G + o000 + 1);
    uint4 b0 = __ldg(G + o001),     b1 = __ldg(G + o001 + 1);
    uint4 c0 = __ldg(G + o010),     c1 = __ldg(G + o010 + 1);
    uint4 d0 = __ldg(G + o011),     d1 = __ldg(G + o011 + 1);
    uint4 e0 = __ldg(G + o100),     e1 = __ldg(G + o100 + 1);
    uint4 f0 = __ldg(G + o101),     f1 = __ldg(G + o101 + 1);
    uint4 h0 = __ldg(G + o110),     h1 = __ldg(G + o110 + 1);
    uint4 i0 = __ldg(G + o111),     i1 = __ldg(G + o111 + 1);

    float r0[8], r1[8];
    {
        float ta[8], tb[8];
        unpack8(a0, ta); unpack8(b0, tb);
        #pragma unroll
        for (int k = 0; k < 8; k++) r0[k] = w000*ta[k] + w001*tb[k];
        unpack8(a1, ta); unpack8(b1, tb);
        #pragma unroll
        for (int k = 0; k < 8; k++) r1[k] = w000*ta[k] + w001*tb[k];
        unpack8(c0, ta); unpack8(d0, tb);
        #pragma unroll
        for (int k = 0; k < 8; k++) r0[k] += w010*ta[k] + w011*tb[k];
        unpack8(c1, ta); unpack8(d1, tb);
        #pragma unroll
        for (int k = 0; k < 8; k++) r1[k] += w010*ta[k] + w011*tb[k];
        unpack8(e0, ta); unpack8(f0, tb);
        #pragma unroll
        for (int k = 0; k < 8; k++) r0[k] += w100*ta[k] + w101*tb[k];
        unpack8(e1, ta); unpack8(f1, tb);
        #pragma unroll
        for (int k = 0; k < 8; k++) r1[k] += w100*ta[k] + w101*tb[k];
        unpack8(h0, ta); unpack8(i0, tb);
        #pragma unroll
        for (int k = 0; k < 8; k++) r0[k] += w110*ta[k] + w111*tb[k];
        unpack8(h1, ta); unpack8(i1, tb);
        #pragma unroll
        for (int k = 0; k < 8; k++) r1[k] += w110*ta[k] + w111*tb[k];
    }

    float4* op = (float4*)(data_out + (size_t)s * CHAN);
    if (sub == 0) {
        // groups 0,1 -> halves 0..15 -> op[0..3]
        __stcs(op + 0, make_float4(r0[0], r0[1], r0[2], r0[3]));
        __stcs(op + 1, make_float4(r0[4], r0[5], r0[6], r0[7]));
        __stcs(op + 2, make_float4(r1[0], r1[1], r1[2], r1[3]));
        __stcs(op + 3, make_float4(r1[4], r1[5], r1[6], r1[7]));
    } else {
        // groups 2,3 -> halves 16..27 -> op[4..6] (skip pad)
        __stcs(op + 4, make_float4(r0[0], r0[1], r0[2], r0[3]));
        __stcs(op + 5, make_float4(r0[4], r0[5], r0[6], r0[7]));
        __stcs(op + 6, make_float4(r1[0], r1[1], r1[2], r1[3]));
        // sub_pts
        float gx = (nx + 1.0f) * 64.0f;
        float gy = (ny + 1.0f) * 64.0f;
        float gz = (nz + 1.0f) * 64.0f;
        float gix = fminf(fmaxf(floorf(gx), 0.0f), 127.0f);
        float giy = fminf(fmaxf(floorf(gy), 0.0f), 127.0f);
        float giz = fminf(fmaxf(floorf(gz), 0.0f), 127.0f);
        __stcs(sub_out + (size_t)s*3+0, gx - gix);
        __stcs(sub_out + (size_t)s*3+1, gy - giy);
        __stcs(sub_out + (size_t)s*3+2, gz - giz);
    }
}

extern "C" void kernel_launch(void* const* d_in, const int* in_sizes, int n_in,
                              void* d_out, int out_size) {
    const float* rays_o = (const float*)d_in[0];
    const float* rays_d = (const float*)d_in[1];
    const float* data   = (const float*)d_in[2];
    float* out = (float*)d_out;

    const long long MASK_N = (long long)N_RAYS * NSAMP;    // 6,287,360
    const long long INTR_N = (long long)N_RAYS * N_INTERS; // 6,291,456
    long long nm = ((long long)out_size - MASK_N - INTR_N) / 31LL;

    float* data_out = out;
    float* mask_out = out + nm * CHAN;
    float* intr_out = mask_out + MASK_N;
    float* sub_out  = intr_out + INTR_N;

    k_pre<<<TR_BLOCKS + N_RAYS, 256>>>(data, rays_o, rays_d, mask_out, intr_out);
    k_scan<<<1, 1024>>>();
    k_build_map<<<N_RAYS, 256>>>();

    long long nthreads = nm * 2;
    int nblocks = (int)((nthreads + 255) / 256);
    k_gather<<<nblocks, 256>>>(data_out, sub_out, (int)nm);
}